// round 2
// baseline (speedup 1.0000x reference)
#include <cuda_runtime.h>
#include <cstdint>
#include <cstddef>

// TemporalAttention: x (B,T,C,H,W) -> per-pixel attention over T.
//   Q = Wq x + bq (D=64), K = Wk x + bk (D=64), S = QK^T/8, A = softmax(S)
//   out = (A @ X) @ Wv^T + bv      (valid because softmax rows sum to 1)
//
// Fused single kernel: 16 pixels per CTA, 256 threads,
// two 128x128x128 register-blocked fp32 GEMMs per CTA.

namespace {
constexpr int kT   = 8;
constexpr int kC   = 128;
constexpr int kHW  = 96 * 96;          // 9216
constexpr int kPIX = 16;               // pixels per CTA
constexpr int kLD  = 136;              // padded row length for conflict relief
constexpr int kTHREADS = 256;
// smem: buf1[128*136] (Wqk^T -> QK -> Ys), buf2[128*136] (Wv^T -> out staging),
//       Xs[128*128], Ssm[1024]
constexpr int kSMEM_FLOATS = 2 * 128 * kLD + 128 * 128 + 1024;
}

__global__ __launch_bounds__(kTHREADS, 1)
void ta_fused(const float* __restrict__ x,
              const float* __restrict__ Wq, const float* __restrict__ bq,
              const float* __restrict__ Wk, const float* __restrict__ bk,
              const float* __restrict__ Wv, const float* __restrict__ bv,
              float* __restrict__ out)
{
    extern __shared__ float sm[];
    float* buf1 = sm;                       // 128 x kLD
    float* buf2 = sm + 128 * kLD;           // 128 x kLD
    float* Xs   = sm + 2 * 128 * kLD;       // [c][m], m = p*8 + t, 128x128
    float* Ssm  = Xs + 128 * 128;           // attn weights, 16*8*8

    const int tid = threadIdx.x;
    const int tx  = tid & 15;
    const int ty  = tid >> 4;
    const int b   = blockIdx.y;
    const int pix0 = blockIdx.x * kPIX;

    // per-thread bias registers for this thread's n-columns
    float bqk[8], bvr[8];
#pragma unroll
    for (int j = 0; j < 4; ++j) {
        bqk[j]     = bq[tx * 4 + j];
        bqk[j + 4] = bk[tx * 4 + j];
        bvr[j]     = bv[tx * 4 + j];
        bvr[j + 4] = bv[64 + tx * 4 + j];
    }

    // ---- stage weights K-major into smem ----
    // buf1[c][n] : n<64 -> Wq[n][c], n>=64 -> Wk[n-64][c]
    for (int i = tid; i < 64 * kC; i += kTHREADS) {
        int n = i >> 7, c = i & 127;
        buf1[c * kLD + n]      = Wq[i];
        buf1[c * kLD + 64 + n] = Wk[i];
    }
    // buf2[c][e] = Wv[e][c]
    for (int i = tid; i < kC * kC; i += kTHREADS) {
        int e = i >> 7, c = i & 127;
        buf2[c * kLD + e] = Wv[i];
    }
    // ---- stage x tile: Xs[c][p*8 + t] = x[b,t,c,pix0+p] ----
    const float* xb = x + (size_t)b * (kT * kC * kHW) + pix0;
    for (int i = tid; i < kT * kC * kPIX; i += kTHREADS) {
        int p  = i & 15;
        int tc = i >> 4;                    // t*128 + c
        int c  = tc & 127;
        Xs[c * 128 + p * 8 + (tc >> 7)] = xb[(size_t)tc * kHW + p];
    }
    __syncthreads();

    // ================= GEMM1: QK[m][n] = sum_c Xs[c][m] * Wqk[c][n] =========
    float acc[8][8];
#pragma unroll
    for (int i = 0; i < 8; ++i)
#pragma unroll
        for (int j = 0; j < 8; ++j) acc[i][j] = 0.f;

#pragma unroll 2
    for (int k = 0; k < 128; ++k) {
        float4 A0 = *(const float4*)&Xs[k * 128 + ty * 4];
        float4 A1 = *(const float4*)&Xs[k * 128 + 64 + ty * 4];
        float4 B0 = *(const float4*)&buf1[k * kLD + tx * 4];
        float4 B1 = *(const float4*)&buf1[k * kLD + 64 + tx * 4];
        float a[8]  = {A0.x, A0.y, A0.z, A0.w, A1.x, A1.y, A1.z, A1.w};
        float bb[8] = {B0.x, B0.y, B0.z, B0.w, B1.x, B1.y, B1.z, B1.w};
#pragma unroll
        for (int i = 0; i < 8; ++i)
#pragma unroll
            for (int j = 0; j < 8; ++j) acc[i][j] += a[i] * bb[j];
    }
    __syncthreads();

    // store Q,K (+bias) into buf1 as QK[m][n] (m-major, padded rows)
#pragma unroll
    for (int i = 0; i < 8; ++i) {
        int m = (i < 4) ? (ty * 4 + i) : (64 + ty * 4 + i - 4);
#pragma unroll
        for (int j = 0; j < 8; ++j) {
            int n = (j < 4) ? (tx * 4 + j) : (64 + tx * 4 + j - 4);
            buf1[m * kLD + n] = acc[i][j] + bqk[j];
        }
    }
    __syncthreads();

    // ================= scores + softmax ====================================
    // warp handles 2 pixels; per pixel, 64 score entries done in two t-halves
    // (32 lanes -> t = (lane>>3) + 4*half, s = lane&7). 8-lane shfl groups
    // share t, reduce over s.
    {
        const int warp = tid >> 5, lane = tid & 31;
        const int tlo = lane >> 3, s = lane & 7;
#pragma unroll
        for (int pi = 0; pi < 2; ++pi) {
            int p = warp * 2 + pi;
#pragma unroll
            for (int half = 0; half < 2; ++half) {
                int t = tlo + half * 4;
                const float* qr = &buf1[(p * 8 + t) * kLD];
                const float* kr = &buf1[(p * 8 + s) * kLD + 64];
                float dot = 0.f;
#pragma unroll
                for (int d = 0; d < 64; d += 4) {
                    float4 q4 = *(const float4*)&qr[d];
                    float4 k4 = *(const float4*)&kr[d];
                    dot += q4.x * k4.x + q4.y * k4.y + q4.z * k4.z + q4.w * k4.w;
                }
                dot *= 0.125f;   // 1/sqrt(64)
                float mx = dot;
#pragma unroll
                for (int o = 1; o < 8; o <<= 1)
                    mx = fmaxf(mx, __shfl_xor_sync(0xffffffffu, mx, o));
                float e = __expf(dot - mx);
                float sum = e;
#pragma unroll
                for (int o = 1; o < 8; o <<= 1)
                    sum += __shfl_xor_sync(0xffffffffu, sum, o);
                Ssm[(p * 8 + t) * 8 + s] = e / sum;
            }
        }
    }
    __syncthreads();

    // ========== Y[c][m] = sum_s attn[p,t,s] * Xs[c][p*8+s]  (into buf1) =====
    {
        const int m  = tid & 127;           // p*8 + t
        const int c0 = (tid >> 7) * 64;
        const int p  = m >> 3;
        float a[8];
#pragma unroll
        for (int s2 = 0; s2 < 8; ++s2) a[s2] = Ssm[m * 8 + s2];
        for (int c = c0; c < c0 + 64; ++c) {
            const float4* xr = (const float4*)&Xs[c * 128 + p * 8];
            float4 x0 = xr[0], x1 = xr[1];
            buf1[c * kLD + m] =
                a[0] * x0.x + a[1] * x0.y + a[2] * x0.z + a[3] * x0.w +
                a[4] * x1.x + a[5] * x1.y + a[6] * x1.z + a[7] * x1.w;
        }
    }
    __syncthreads();

    // ========== GEMM3: out[m][e] = sum_c Ys[c][m] * Wv[e][c] ================
#pragma unroll
    for (int i = 0; i < 8; ++i)
#pragma unroll
        for (int j = 0; j < 8; ++j) acc[i][j] = 0.f;

#pragma unroll 2
    for (int k = 0; k < 128; ++k) {
        float4 A0 = *(const float4*)&buf1[k * kLD + ty * 4];
        float4 A1 = *(const float4*)&buf1[k * kLD + 64 + ty * 4];
        float4 B0 = *(const float4*)&buf2[k * kLD + tx * 4];
        float4 B1 = *(const float4*)&buf2[k * kLD + 64 + tx * 4];
        float a[8]  = {A0.x, A0.y, A0.z, A0.w, A1.x, A1.y, A1.z, A1.w};
        float bb[8] = {B0.x, B0.y, B0.z, B0.w, B1.x, B1.y, B1.z, B1.w};
#pragma unroll
        for (int i = 0; i < 8; ++i)
#pragma unroll
            for (int j = 0; j < 8; ++j) acc[i][j] += a[i] * bb[j];
    }
    __syncthreads();

    // stage result (+bias) into buf2 as Os[(t*128+e)*16 + p] for coalesced stores
#pragma unroll
    for (int i = 0; i < 8; ++i) {
        int m = (i < 4) ? (ty * 4 + i) : (64 + ty * 4 + i - 4);
        int p = m >> 3, t = m & 7;
#pragma unroll
        for (int j = 0; j < 8; ++j) {
            int n = (j < 4) ? (tx * 4 + j) : (64 + tx * 4 + j - 4);
            buf2[(t * 128 + n) * 16 + p] = acc[i][j] + bvr[j];
        }
    }
    __syncthreads();

    // ========== coalesced gmem write: out[b,t,e,pix0+p] ======================
    {
        float* ob = out + (size_t)b * (kT * kC * kHW) + pix0;
        const int p = tid & 15, g = tid >> 4;
#pragma unroll 4
        for (int it = 0; it < 64; ++it) {
            int q = it * 16 + g;            // q = t*128 + e
            ob[(size_t)q * kHW + p] = buf2[q * 16 + p];
        }
    }
}

extern "C" void kernel_launch(void* const* d_in, const int* in_sizes, int n_in,
                              void* d_out, int out_size)
{
    const float* x  = (const float*)d_in[0];
    const float* Wq = (const float*)d_in[1];
    const float* bq = (const float*)d_in[2];
    const float* Wk = (const float*)d_in[3];
    const float* bk = (const float*)d_in[4];
    const float* Wv = (const float*)d_in[5];
    const float* bv = (const float*)d_in[6];
    float* out = (float*)d_out;

    const int B = in_sizes[0] / (kT * kC * kHW);
    const size_t smem = kSMEM_FLOATS * sizeof(float);
    cudaFuncSetAttribute(ta_fused, cudaFuncAttributeMaxDynamicSharedMemorySize,
                         (int)smem);
    dim3 grid(kHW / kPIX, B);
    ta_fused<<<grid, kTHREADS, smem>>>(x, Wq, bq, Wk, bk, Wv, bv, out);
}